// round 11
// baseline (speedup 1.0000x reference)
#include <cuda_runtime.h>
#include <cuda_bf16.h>
#include <cstdint>

// Problem constants
#define BS      16
#define C_TOT   512
#define HW      1024
#define N_TOT   16384
#define M_SUB   8
#define NE      1024
#define E_DIM   64

// Tiling
#define TM      128            // z rows per CTA
#define KC      64             // codes per chunk
#define NCH     (NE / KC)      // 16
#define MARGIN  6e-5f          // covers worst-case 2*(2*dot_err)+2*ulp(64)

// Output layout (float32, tuple-concatenated)
#define OUT_LOSS 8388608
#define OUT_IDX  8388609
#define OUT_BIN  (OUT_IDX + M_SUB * N_TOT)

// Scratch (static; no cudaMalloc allowed)
__device__ int   g_idx[M_SUB * N_TOT];
__device__ float g_rowdist[M_SUB * N_TOT];
__device__ int   g_bins[NE];
__device__ int   g_fbcnt[M_SUB];
__device__ int   g_fblist[M_SUB][N_TOT];

// ---- dynamic smem word map (u32 units) ----
// zsh  [2 split][128 row][36 w]   bf16x2 words, stride 36 -> bank==lane frag loads
// esh  [2 buf][2 split][64][36]
// raw  [2 buf][64 code][64 d] float
// en   [2 buf][64]; zn [128]; znp [2][128]   (disjoint regions)
#define W_ZSH 0
#define W_ESH 9216
#define W_RAW 18432
#define W_EN  26624
#define W_ZN  26752
#define W_ZNP 26880
#define SMEM_WORDS 27136
#define SMEM_BYTES (SMEM_WORDS * 4)    // 108544 B -> 2 CTAs/SM

__device__ __forceinline__ void cp_async16(uint32_t saddr, const void* gptr) {
    asm volatile("cp.async.cg.shared.global [%0], [%1], 16;" :: "r"(saddr), "l"(gptr));
}
#define CP_COMMIT() asm volatile("cp.async.commit_group;")
#define CP_WAIT(n)  asm volatile("cp.async.wait_group %0;" :: "n"(n))

__device__ __forceinline__ void mma_bf16(float* c, const uint32_t* a,
                                         uint32_t b0, uint32_t b1) {
    asm volatile(
        "mma.sync.aligned.m16n8k16.row.col.f32.bf16.bf16.f32 "
        "{%0,%1,%2,%3}, {%4,%5,%6,%7}, {%8,%9}, {%0,%1,%2,%3};"
        : "+f"(c[0]), "+f"(c[1]), "+f"(c[2]), "+f"(c[3])
        : "r"(a[0]), "r"(a[1]), "r"(a[2]), "r"(a[3]), "r"(b0), "r"(b1));
}

__device__ __forceinline__ uint32_t pack2(float a, float b) {
    __nv_bfloat162 t = __floats2bfloat162_rn(a, b);
    return *reinterpret_cast<uint32_t*>(&t);
}
__device__ __forceinline__ void split1(float v, float& hi, float& lo) {
    __nv_bfloat16 h = __float2bfloat16_rn(v);
    hi = __bfloat162float(h);
    lo = v - hi;                       // exact in fp32
}

// ---------------------------------------------------------------------------
__global__ void vq_init_kernel() {
    int t = blockIdx.x * 256 + threadIdx.x;
    if (t < NE) g_bins[t] = 0;
    if (t >= NE && t < NE + M_SUB) g_fbcnt[t - NE] = 0;
}

// ---------------------------------------------------------------------------
// Tensor kernel: bf16-split mma.sync GEMM (3 products: Ah*Bh + Al*Bh + Ah*Bl)
// over all 1024 codes, per-row argmin with second-min margin.
// dist = fl(fl(zn+en) - 2*dot~); |dist - ref_dist| <= 2*dot_err + ulp(64).
// Rows with (min2 - min1) <= MARGIN are re-solved exactly by the fallback;
// unflagged rows cannot flip. Per-thread code order ascending + strict < =>
// lowest-index tie-break; cross-lane merges tie-break explicitly.
// ---------------------------------------------------------------------------
__global__ __launch_bounds__(256, 2)
void vq_tensor_kernel(const float* __restrict__ z, const float* __restrict__ cb)
{
    extern __shared__ __align__(16) uint32_t sm[];
    float* smf = reinterpret_cast<float*>(sm);
    __nv_bfloat16* smh = reinterpret_cast<__nv_bfloat16*>(sm);

    const int tid = threadIdx.x;
    const int w = tid >> 5, lane = tid & 31, g = lane >> 2, tg = lane & 3;
    const int m = blockIdx.y, tile = blockIdx.x;
    const int n_base = tile * TM, b = n_base >> 10, hw0 = n_base & 1023;

    uint32_t raw_base = (uint32_t)__cvta_generic_to_shared(sm + W_RAW);
    const float4* cb4 = reinterpret_cast<const float4*>(cb + (size_t)m * NE * E_DIM);

    // prologue: async-stage codebook chunks 0 and 1
    #pragma unroll
    for (int c = 0; c < 2; c++) {
        #pragma unroll
        for (int q = 0; q < 4; q++) {
            int idx4 = tid + q * 256;                        // code*16 + d4
            cp_async16(raw_base + (uint32_t)(c * 4096 + idx4 * 4) * 4,
                       cb4 + c * 1024 + idx4);
        }
        CP_COMMIT();
    }

    // A fill: split z into bf16 hi/lo, gather znorm partials
    {
        const int row = tid & 127, h = tid >> 7;
        const float* zsrc = z + (size_t)(b * C_TOT + m * E_DIM) * HW + hw0;
        float part = 0.f;
        #pragma unroll
        for (int i = 0; i < 32; i++) {
            int d = h + 2 * i;
            float v = zsrc[(size_t)d * HW + row];
            part += v * v;
            float hi, lo; split1(v, hi, lo);
            smh[row * 72 + d]        = __float2bfloat16_rn(hi);
            smh[9216 + row * 72 + d] = __float2bfloat16_rn(lo);
        }
        smf[W_ZNP + h * 128 + row] = part;
    }
    __syncthreads();
    if (tid < 128) smf[W_ZN + tid] = smf[W_ZNP + tid] + smf[W_ZNP + 128 + tid];
    __syncthreads();

    // A fragments (registers, reused all chunks) + zn registers
    const int r0 = w * 16 + g;
    const float zn0 = smf[W_ZN + r0], zn1 = smf[W_ZN + r0 + 8];
    uint32_t af[2][4][4];
    #pragma unroll
    for (int s = 0; s < 2; s++)
        #pragma unroll
        for (int ks = 0; ks < 4; ks++) {
            int base = W_ZSH + s * 4608 + ks * 8 + tg;
            af[s][ks][0] = sm[base + r0 * 36];
            af[s][ks][1] = sm[base + (r0 + 8) * 36];
            af[s][ks][2] = sm[base + r0 * 36 + 4];
            af[s][ks][3] = sm[base + (r0 + 8) * 36 + 4];
        }

    float b1v0 = 3.4e38f, b2v0 = 3.4e38f, b1v1 = 3.4e38f, b2v1 = 3.4e38f;
    int   bi0 = 0, bi1 = 0;

    for (int ch = 0; ch < NCH; ch++) {
        const int buf = ch & 1;
        if (ch == NCH - 1) { CP_WAIT(0); } else { CP_WAIT(1); }
        __syncthreads();                     // raw[buf] visible to all

        // convert raw[buf] -> esh[buf] (hi/lo) + en[buf] via quad shuffle
        {
            const int code = tid >> 2, part = tid & 3;
            const float4* rf4 = reinterpret_cast<const float4*>(
                smf + W_RAW + buf * 4096 + code * 64 + part * 16);
            float en = 0.f;
            int whi = W_ESH + (buf * 2 + 0) * 2304 + code * 36 + part * 8;
            int wlo = W_ESH + (buf * 2 + 1) * 2304 + code * 36 + part * 8;
            #pragma unroll
            for (int q = 0; q < 4; q++) {
                float4 v = rf4[q];
                en += v.x * v.x + v.y * v.y + v.z * v.z + v.w * v.w;
                float hx, lx, hy, ly, hz, lz, hw_, lw_;
                split1(v.x, hx, lx); split1(v.y, hy, ly);
                split1(v.z, hz, lz); split1(v.w, hw_, lw_);
                sm[whi + q * 2]     = pack2(hx, hy);
                sm[whi + q * 2 + 1] = pack2(hz, hw_);
                sm[wlo + q * 2]     = pack2(lx, ly);
                sm[wlo + q * 2 + 1] = pack2(lz, lw_);
            }
            en += __shfl_xor_sync(0xffffffffu, en, 1);
            en += __shfl_xor_sync(0xffffffffu, en, 2);
            if (part == 0) smf[W_EN + buf * 64 + code] = en;
        }
        __syncthreads();                     // esh/en ready; raw[buf] free

        if (ch + 2 < NCH) {
            const float4* src = cb4 + (ch + 2) * 1024;
            #pragma unroll
            for (int q = 0; q < 4; q++) {
                int idx4 = tid + q * 256;
                cp_async16(raw_base + (uint32_t)(buf * 4096 + idx4 * 4) * 4,
                           src + idx4);
            }
            CP_COMMIT();
        }

        // ---- MMA: 8 ntiles x 4 ksteps x 3 split-products ----
        float acc[8][4];
        #pragma unroll
        for (int nt = 0; nt < 8; nt++)
            acc[nt][0] = acc[nt][1] = acc[nt][2] = acc[nt][3] = 0.f;

        #pragma unroll
        for (int ks = 0; ks < 4; ks++) {
            #pragma unroll
            for (int nt = 0; nt < 8; nt++) {
                int wb = W_ESH + (nt * 8 + g) * 36 + ks * 8 + tg;
                uint32_t bh0 = sm[wb + (buf * 2 + 0) * 2304];
                uint32_t bh1 = sm[wb + (buf * 2 + 0) * 2304 + 4];
                uint32_t bl0 = sm[wb + (buf * 2 + 1) * 2304];
                uint32_t bl1 = sm[wb + (buf * 2 + 1) * 2304 + 4];
                mma_bf16(acc[nt], af[0][ks], bh0, bh1);   // Ah*Bh
                mma_bf16(acc[nt], af[1][ks], bh0, bh1);   // Al*Bh
                mma_bf16(acc[nt], af[0][ks], bl0, bl1);   // Ah*Bl
            }
        }

        // ---- epilogue: dist + (b1,b2,bi) per row ----
        #pragma unroll
        for (int nt = 0; nt < 8; nt++) {
            float en0 = smf[W_EN + buf * 64 + nt * 8 + tg * 2];
            float en1 = smf[W_EN + buf * 64 + nt * 8 + tg * 2 + 1];
            int k0 = ch * 64 + nt * 8 + tg * 2;
            float d00 = __fmaf_rn(-2.f, acc[nt][0], __fadd_rn(zn0, en0));
            float d01 = __fmaf_rn(-2.f, acc[nt][1], __fadd_rn(zn0, en1));
            float d10 = __fmaf_rn(-2.f, acc[nt][2], __fadd_rn(zn1, en0));
            float d11 = __fmaf_rn(-2.f, acc[nt][3], __fadd_rn(zn1, en1));
            if (d00 < b1v0) { b2v0 = b1v0; b1v0 = d00; bi0 = k0; }     else if (d00 < b2v0) b2v0 = d00;
            if (d01 < b1v0) { b2v0 = b1v0; b1v0 = d01; bi0 = k0 + 1; } else if (d01 < b2v0) b2v0 = d01;
            if (d10 < b1v1) { b2v1 = b1v1; b1v1 = d10; bi1 = k0; }     else if (d10 < b2v1) b2v1 = d10;
            if (d11 < b1v1) { b2v1 = b1v1; b1v1 = d11; bi1 = k0 + 1; } else if (d11 < b2v1) b2v1 = d11;
        }
    }

    // quad reduce (lanes tg 0..3 share rows r0/r0+8); merge keeps true 2nd-min
    #pragma unroll
    for (int off = 1; off <= 2; off <<= 1) {
        float o1 = __shfl_xor_sync(0xffffffffu, b1v0, off);
        float o2 = __shfl_xor_sync(0xffffffffu, b2v0, off);
        int   oi = __shfl_xor_sync(0xffffffffu, bi0, off);
        if (o1 < b1v0 || (o1 == b1v0 && oi < bi0)) { b2v0 = fminf(b1v0, o2); b1v0 = o1; bi0 = oi; }
        else b2v0 = fminf(b2v0, o1);
        float p1 = __shfl_xor_sync(0xffffffffu, b1v1, off);
        float p2 = __shfl_xor_sync(0xffffffffu, b2v1, off);
        int   pi = __shfl_xor_sync(0xffffffffu, bi1, off);
        if (p1 < b1v1 || (p1 == b1v1 && pi < bi1)) { b2v1 = fminf(b1v1, p2); b1v1 = p1; bi1 = pi; }
        else b2v1 = fminf(b2v1, p1);
    }

    if (tg == 0) {
        int rr = m * N_TOT + n_base + r0;
        g_idx[rr] = bi0; g_rowdist[rr] = b1v0;
        if (b2v0 - b1v0 <= MARGIN) { int p = atomicAdd(&g_fbcnt[m], 1); g_fblist[m][p] = n_base + r0; }
        rr += 8;
        g_idx[rr] = bi1; g_rowdist[rr] = b1v1;
        if (b2v1 - b1v1 <= MARGIN) { int p = atomicAdd(&g_fbcnt[m], 1); g_fblist[m][p] = n_base + r0 + 8; }
    }
}

// ---------------------------------------------------------------------------
// Exact fp32 fallback, 8 rows per codebook pass (shares code reads).
// Semantics identical to the R5-validated exact kernel.
// ---------------------------------------------------------------------------
__global__ __launch_bounds__(256)
void vq_fallback_kernel(const float* __restrict__ z, const float* __restrict__ cb)
{
    __shared__ float zr[8][64];
    __shared__ float zns[8];
    __shared__ int   srow[8];
    __shared__ float rbv[8][256];
    __shared__ int   rbi[8][256];
    const int tid = threadIdx.x;
    const int m = blockIdx.y;
    const int cnt = g_fbcnt[m];

    for (int base = blockIdx.x * 8; base < cnt; base += gridDim.x * 8) {
        int nrows = min(8, cnt - base);
        if (tid < 8) srow[tid] = g_fblist[m][(tid < nrows) ? base + tid : base];
        __syncthreads();
        for (int t = tid; t < 8 * 64; t += 256) {
            int j = t >> 6, d = t & 63, n = srow[j];
            zr[j][d] = z[(size_t)((n >> 10) * C_TOT + m * E_DIM + d) * HW + (n & 1023)];
        }
        __syncthreads();
        if (tid < 8) {
            float s = 0.f;
            for (int d = 0; d < 64; d++) s = __fmaf_rn(zr[tid][d], zr[tid][d], s);
            zns[tid] = s;
        }
        __syncthreads();

        float b1[8]; int bi[8];
        #pragma unroll
        for (int j = 0; j < 8; j++) { b1[j] = 3.4e38f; bi[j] = 0; }

        for (int kq = 0; kq < 4; kq++) {
            int c = tid + kq * 256;                       // ascending per thread
            const float4* cr = reinterpret_cast<const float4*>(
                cb + ((size_t)m * NE + c) * E_DIM);
            float en = 0.f; float dot[8];
            #pragma unroll
            for (int j = 0; j < 8; j++) dot[j] = 0.f;
            #pragma unroll
            for (int q = 0; q < 16; q++) {
                float4 e = cr[q];
                en = __fmaf_rn(e.x, e.x, __fmaf_rn(e.y, e.y,
                     __fmaf_rn(e.z, e.z, __fmaf_rn(e.w, e.w, en))));
                #pragma unroll
                for (int j = 0; j < 8; j++) {
                    dot[j] = __fmaf_rn(zr[j][q * 4 + 0], e.x, dot[j]);
                    dot[j] = __fmaf_rn(zr[j][q * 4 + 1], e.y, dot[j]);
                    dot[j] = __fmaf_rn(zr[j][q * 4 + 2], e.z, dot[j]);
                    dot[j] = __fmaf_rn(zr[j][q * 4 + 3], e.w, dot[j]);
                }
            }
            #pragma unroll
            for (int j = 0; j < 8; j++) {
                float dist = __fmaf_rn(-2.f, dot[j], __fadd_rn(zns[j], en));
                if (dist < b1[j]) { b1[j] = dist; bi[j] = c; }
            }
        }
        #pragma unroll
        for (int j = 0; j < 8; j++) { rbv[j][tid] = b1[j]; rbi[j][tid] = bi[j]; }
        __syncthreads();

        int wj = tid >> 5, lane = tid & 31;
        {
            float v = rbv[wj][lane]; int i0 = rbi[wj][lane];
            #pragma unroll
            for (int k = 1; k < 8; k++) {
                float ov = rbv[wj][lane + 32 * k]; int oi = rbi[wj][lane + 32 * k];
                if (ov < v || (ov == v && oi < i0)) { v = ov; i0 = oi; }
            }
            #pragma unroll
            for (int off = 16; off >= 1; off >>= 1) {
                float ov = __shfl_xor_sync(0xffffffffu, v, off);
                int   oi = __shfl_xor_sync(0xffffffffu, i0, off);
                if (ov < v || (ov == v && oi < i0)) { v = ov; i0 = oi; }
            }
            if (lane == 0 && wj < nrows) {
                int n = srow[wj];
                g_idx[m * N_TOT + n] = i0;
                g_rowdist[m * N_TOT + n] = v;
            }
        }
        __syncthreads();
    }
}

// ---------------------------------------------------------------------------
// Scatter: gather chosen codes, straight-through rounding bit-exact
// (zq_st = fl(zf + fl(zq - zf))), scatter to NCHW, histogram. (R5-validated)
// ---------------------------------------------------------------------------
#define ZS_STRIDE 68
__global__ __launch_bounds__(256)
void vq_scatter_kernel(const float* __restrict__ z, const float* __restrict__ cb,
                       float* __restrict__ out)
{
    __shared__ float cs[TM][ZS_STRIDE];
    __shared__ int   sidx[TM];
    const int tid = threadIdx.x;
    const int m = blockIdx.y, tile = blockIdx.x;
    const int n_base = tile * TM, b = n_base >> 10, hw0 = n_base & 1023;

    if (tid < TM) {
        int v = g_idx[m * N_TOT + n_base + tid];
        sidx[tid] = v;
        atomicAdd(&g_bins[v], 1);
    }
    __syncthreads();
    const float4* cb4 = reinterpret_cast<const float4*>(cb + (size_t)m * NE * E_DIM);
    for (int idx4 = tid; idx4 < TM * 16; idx4 += 256) {
        int r = idx4 >> 4, d4 = idx4 & 15;
        float4 v = cb4[sidx[r] * 16 + d4];
        *reinterpret_cast<float4*>(&cs[r][d4 * 4]) = v;
    }
    __syncthreads();
    const float* zsrc = z   + (size_t)(b * C_TOT + m * E_DIM) * HW + hw0;
    float*       dst  = out + (size_t)(b * C_TOT + m * E_DIM) * HW + hw0;
    for (int idx = tid; idx < E_DIM * TM; idx += 256) {
        int d = idx >> 7, nl = idx & 127;
        size_t off = (size_t)d * HW + nl;
        float zv = zsrc[off];
        float t  = __fsub_rn(cs[nl][d], zv);
        dst[off] = __fadd_rn(zv, t);
    }
}

// ---------------------------------------------------------------------------
__global__ __launch_bounds__(256)
void vq_final_kernel(float* __restrict__ out)
{
    if (blockIdx.x == 0) {
        __shared__ float part[256];
        int tid = threadIdx.x;
        float s = 0.f;
        for (int i = tid; i < M_SUB * N_TOT; i += 256) s += g_rowdist[i];
        part[tid] = s;
        __syncthreads();
        if (tid == 0) {
            float t = 0.f;
            for (int q = 0; q < 256; q++) t += part[q];
            out[OUT_LOSS] = t * (1.25f / (float)(N_TOT * E_DIM));
        }
    } else {
        int off = (blockIdx.x - 1) * 256 + threadIdx.x;
        if (off < M_SUB * N_TOT) {
            out[OUT_IDX + off] = (float)g_idx[off];
        } else {
            int bo = off - M_SUB * N_TOT;
            if (bo < NE) out[OUT_BIN + bo] = (float)g_bins[bo];
        }
    }
}

// ---------------------------------------------------------------------------
extern "C" void kernel_launch(void* const* d_in, const int* in_sizes, int n_in,
                              void* d_out, int out_size)
{
    const float* z  = (const float*)d_in[0];
    const float* cb = (const float*)d_in[1];
    float* out = (float*)d_out;

    cudaFuncSetAttribute(vq_tensor_kernel,
                         cudaFuncAttributeMaxDynamicSharedMemorySize, SMEM_BYTES);

    vq_init_kernel<<<5, 256>>>();

    dim3 gridT(N_TOT / TM, M_SUB);            // 128 x 8
    vq_tensor_kernel<<<gridT, 256, SMEM_BYTES>>>(z, cb);

    dim3 gridF(32, M_SUB);
    vq_fallback_kernel<<<gridF, 256>>>(z, cb);

    dim3 gridS(N_TOT / TM, M_SUB);
    vq_scatter_kernel<<<gridS, 256>>>(z, cb, out);

    int conv_elems = M_SUB * N_TOT + NE;
    int gridC = 1 + (conv_elems + 255) / 256;
    vq_final_kernel<<<gridC, 256>>>(out);
}

// round 12
// speedup vs baseline: 1.5770x; 1.5770x over previous
#include <cuda_runtime.h>
#include <cuda_bf16.h>
#include <cstdint>

// Problem constants
#define BS      16
#define C_TOT   512
#define HW      1024
#define N_TOT   16384
#define M_SUB   8
#define NE      1024
#define E_DIM   64

// Tiling
#define TM      128            // z rows per CTA
#define KC      64             // codes per chunk
#define NCH     (NE / KC)      // 16
#define MARGIN  6e-5f          // >= worst-case cross-scale ordering discrepancy

// Output layout (float32, tuple-concatenated)
#define OUT_LOSS 8388608
#define OUT_IDX  8388609
#define OUT_BIN  (OUT_IDX + M_SUB * N_TOT)

// Scratch (static; no cudaMalloc allowed)
__device__ int   g_idx[M_SUB * N_TOT];
__device__ float g_rowdist[M_SUB * N_TOT];       // dist' = en - 2*dot (no zn)
__device__ int   g_bins[NE];
__device__ int   g_fbcnt[M_SUB];
__device__ int   g_fblist[M_SUB][N_TOT];
__device__ float g_zpart[1024];                  // per-(m,tile) sum of z^2
// pre-split codebook: [m*NE + code][split(2)][32 words of bf16x2]
__device__ __align__(16) uint32_t g_cbsplit[M_SUB * NE * 64];
__device__ __align__(16) float    g_en[M_SUB * NE];

// ---- tensor-kernel smem word map (u32 units) ----
// zsh (A staging, 2 splits x 128 rows x 36w) occupies words 0..9215;
// B buf1 (2 splits x 64 codes x 36w = 4608w) OVERLAYS words 0..4607 (zsh is
// dead after A-frags are loaded into registers, before buf1's first fill).
// B buf0 at 9216..13823 (disjoint from zsh: filled during A staging).
#define W_B1  0
#define W_B0  9216
#define W_EN  13824            // [2 buf][64] floats
#define SMEM_WORDS 13952
#define SMEM_BYTES (SMEM_WORDS * 4)   // 55808 B

__device__ __forceinline__ void cp_async16(uint32_t saddr, const void* gptr) {
    asm volatile("cp.async.cg.shared.global [%0], [%1], 16;" :: "r"(saddr), "l"(gptr));
}
#define CP_COMMIT() asm volatile("cp.async.commit_group;")
#define CP_WAIT(n)  asm volatile("cp.async.wait_group %0;" :: "n"(n))

__device__ __forceinline__ void mma_bf16(float* c, const uint32_t* a,
                                         uint32_t b0, uint32_t b1) {
    asm volatile(
        "mma.sync.aligned.m16n8k16.row.col.f32.bf16.bf16.f32 "
        "{%0,%1,%2,%3}, {%4,%5,%6,%7}, {%8,%9}, {%0,%1,%2,%3};"
        : "+f"(c[0]), "+f"(c[1]), "+f"(c[2]), "+f"(c[3])
        : "r"(a[0]), "r"(a[1]), "r"(a[2]), "r"(a[3]), "r"(b0), "r"(b1));
}

__device__ __forceinline__ uint32_t pack2(float a, float b) {
    __nv_bfloat162 t = __floats2bfloat162_rn(a, b);
    return *reinterpret_cast<uint32_t*>(&t);
}
__device__ __forceinline__ void split1(float v, float& hi, float& lo) {
    __nv_bfloat16 h = __float2bfloat16_rn(v);
    hi = __bfloat162float(h);
    lo = v - hi;                       // exact in fp32
}

// ---------------------------------------------------------------------------
__global__ void vq_init_kernel() {
    int t = blockIdx.x * 256 + threadIdx.x;
    if (t < NE) g_bins[t] = 0;
    if (t >= NE && t < NE + M_SUB) g_fbcnt[t - NE] = 0;
}

// ---------------------------------------------------------------------------
// Precompute: split codebook to bf16 hi/lo planes (mma-ready layout) + ||e||^2.
// ---------------------------------------------------------------------------
__global__ __launch_bounds__(256)
void vq_precompute_kernel(const float* __restrict__ cb)
{
    int t = blockIdx.x * 256 + threadIdx.x;      // 8192 codes total
    if (t >= M_SUB * NE) return;
    const float4* src = reinterpret_cast<const float4*>(cb + (size_t)t * E_DIM);
    uint32_t* dst = g_cbsplit + (size_t)t * 64;  // [split][32w]
    float en = 0.f;
    #pragma unroll
    for (int q = 0; q < 16; q++) {
        float4 v = src[q];
        en += v.x * v.x + v.y * v.y + v.z * v.z + v.w * v.w;
        float hx, lx, hy, ly, hz, lz, hw_, lw_;
        split1(v.x, hx, lx); split1(v.y, hy, ly);
        split1(v.z, hz, lz); split1(v.w, hw_, lw_);
        dst[q * 2]          = pack2(hx, hy);
        dst[q * 2 + 1]      = pack2(hz, hw_);
        dst[32 + q * 2]     = pack2(lx, ly);
        dst[32 + q * 2 + 1] = pack2(lz, lw_);
    }
    g_en[t] = en;
}

// ---------------------------------------------------------------------------
// Tensor kernel: bf16-split mma.sync (3 products), per-row argmin on
// dist' = en - 2*dot (row-constant zn dropped; ordering preserved within
// MARGIN, flagged rows re-solved exactly). Product-major MMA bursts give 8
// independent accumulator chains. B panels arrive pre-split via cp.async.
// Per-thread code order ascending + strict < => lowest-index tie-break.
// ---------------------------------------------------------------------------
__global__ __launch_bounds__(256, 2)
void vq_tensor_kernel(const float* __restrict__ z)
{
    extern __shared__ __align__(16) uint32_t sm[];
    float* smf = reinterpret_cast<float*>(sm);
    __nv_bfloat16* smh = reinterpret_cast<__nv_bfloat16*>(sm);

    const int tid = threadIdx.x;
    const int w = tid >> 5, lane = tid & 31, g = lane >> 2, tg = lane & 3;
    const int m = blockIdx.y, tile = blockIdx.x;
    const int n_base = tile * TM, b = n_base >> 10, hw0 = n_base & 1023;

    const uint32_t sbase = (uint32_t)__cvta_generic_to_shared(sm);

    // prefetch one chunk's pre-split panels + en into buf
    auto prefetch = [&](int ch, int buf) {
        const uint32_t bw = buf ? W_B1 : W_B0;
        const uint32_t* src = g_cbsplit + ((size_t)m * NE + ch * KC) * 64;
        #pragma unroll
        for (int q = 0; q < 4; q++) {
            int idx = q * 256 + tid;                 // 0..1023
            int split = idx >> 9, code = (idx >> 3) & 63, p = idx & 7;
            uint32_t dw = bw + split * 2304 + code * 36 + p * 4;
            cp_async16(sbase + dw * 4, src + (size_t)code * 64 + split * 32 + p * 4);
        }
        if (tid < 16)
            cp_async16(sbase + (W_EN + buf * 64 + tid * 4) * 4,
                       g_en + m * NE + ch * KC + tid * 4);
        CP_COMMIT();
    };

    // chunk 0 -> buf0 (disjoint from A staging area)
    prefetch(0, 0);

    // stage A: split z rows into bf16 hi/lo planes at words 0..9215
    {
        const int row = tid & 127, h = tid >> 7;
        const float* zsrc = z + (size_t)(b * C_TOT + m * E_DIM) * HW + hw0;
        #pragma unroll
        for (int i = 0; i < 32; i++) {
            int d = h + 2 * i;
            float v = zsrc[(size_t)d * HW + row];
            float hi, lo; split1(v, hi, lo);
            smh[row * 72 + d]        = __float2bfloat16_rn(hi);
            smh[9216 + row * 72 + d] = __float2bfloat16_rn(lo);
        }
    }
    __syncthreads();

    // A fragments -> registers (reused for all 16 chunks)
    const int r0 = w * 16 + g;
    uint32_t af[2][4][4];
    #pragma unroll
    for (int s = 0; s < 2; s++)
        #pragma unroll
        for (int ks = 0; ks < 4; ks++) {
            int base = s * 4608 + ks * 8 + tg;
            af[s][ks][0] = sm[base + r0 * 36];
            af[s][ks][1] = sm[base + (r0 + 8) * 36];
            af[s][ks][2] = sm[base + r0 * 36 + 4];
            af[s][ks][3] = sm[base + (r0 + 8) * 36 + 4];
        }
    __syncthreads();          // zsh fully consumed; buf1 region now writable

    prefetch(1, 1);

    float b1v0 = 3.4e38f, b2v0 = 3.4e38f, b1v1 = 3.4e38f, b2v1 = 3.4e38f;
    int   bi0 = 0, bi1 = 0;
    const int boff = g * 36 + tg;

    for (int ch = 0; ch < NCH; ch++) {
        const int buf = ch & 1;
        const uint32_t bw = buf ? W_B1 : W_B0;
        if (ch == NCH - 1) { CP_WAIT(0); } else { CP_WAIT(1); }
        __syncthreads();                         // panels[buf] + en[buf] visible

        float acc[8][4];
        #pragma unroll
        for (int nt = 0; nt < 8; nt++)
            acc[nt][0] = acc[nt][1] = acc[nt][2] = acc[nt][3] = 0.f;

        #pragma unroll
        for (int ks = 0; ks < 4; ks++) {
            const int kb = bw + ks * 8 + boff;
            uint32_t bh[8][2];
            #pragma unroll
            for (int nt = 0; nt < 8; nt++) {
                bh[nt][0] = sm[kb + nt * 288];
                bh[nt][1] = sm[kb + nt * 288 + 4];
            }
            #pragma unroll
            for (int nt = 0; nt < 8; nt++)       // Ah*Bh: 8 independent
                mma_bf16(acc[nt], af[0][ks], bh[nt][0], bh[nt][1]);
            #pragma unroll
            for (int nt = 0; nt < 8; nt++)       // Al*Bh: reuse frags
                mma_bf16(acc[nt], af[1][ks], bh[nt][0], bh[nt][1]);
            uint32_t bl[8][2];
            #pragma unroll
            for (int nt = 0; nt < 8; nt++) {
                bl[nt][0] = sm[kb + 2304 + nt * 288];
                bl[nt][1] = sm[kb + 2304 + nt * 288 + 4];
            }
            #pragma unroll
            for (int nt = 0; nt < 8; nt++)       // Ah*Bl
                mma_bf16(acc[nt], af[0][ks], bl[nt][0], bl[nt][1]);
        }

        // epilogue: dist' = en - 2*dot; track (min1, min2, idx) per row
        const float* enp = smf + W_EN + buf * 64;
        #pragma unroll
        for (int nt = 0; nt < 8; nt++) {
            float en0 = enp[nt * 8 + tg * 2];
            float en1 = enp[nt * 8 + tg * 2 + 1];
            int k0 = ch * 64 + nt * 8 + tg * 2;
            float d00 = __fmaf_rn(-2.f, acc[nt][0], en0);
            float d01 = __fmaf_rn(-2.f, acc[nt][1], en1);
            float d10 = __fmaf_rn(-2.f, acc[nt][2], en0);
            float d11 = __fmaf_rn(-2.f, acc[nt][3], en1);
            if (d00 < b1v0) { b2v0 = b1v0; b1v0 = d00; bi0 = k0; }     else if (d00 < b2v0) b2v0 = d00;
            if (d01 < b1v0) { b2v0 = b1v0; b1v0 = d01; bi0 = k0 + 1; } else if (d01 < b2v0) b2v0 = d01;
            if (d10 < b1v1) { b2v1 = b1v1; b1v1 = d10; bi1 = k0; }     else if (d10 < b2v1) b2v1 = d10;
            if (d11 < b1v1) { b2v1 = b1v1; b1v1 = d11; bi1 = k0 + 1; } else if (d11 < b2v1) b2v1 = d11;
        }
        __syncthreads();                         // all reads of buf done
        if (ch + 2 < NCH) prefetch(ch + 2, buf);
    }

    // quad reduce (lanes tg 0..3 share rows r0 / r0+8); keeps true 2nd-min
    #pragma unroll
    for (int off = 1; off <= 2; off <<= 1) {
        float o1 = __shfl_xor_sync(0xffffffffu, b1v0, off);
        float o2 = __shfl_xor_sync(0xffffffffu, b2v0, off);
        int   oi = __shfl_xor_sync(0xffffffffu, bi0, off);
        if (o1 < b1v0 || (o1 == b1v0 && oi < bi0)) { b2v0 = fminf(b1v0, o2); b1v0 = o1; bi0 = oi; }
        else b2v0 = fminf(b2v0, o1);
        float p1 = __shfl_xor_sync(0xffffffffu, b1v1, off);
        float p2 = __shfl_xor_sync(0xffffffffu, b2v1, off);
        int   pi = __shfl_xor_sync(0xffffffffu, bi1, off);
        if (p1 < b1v1 || (p1 == b1v1 && pi < bi1)) { b2v1 = fminf(b1v1, p2); b1v1 = p1; bi1 = pi; }
        else b2v1 = fminf(b2v1, p1);
    }

    if (tg == 0) {
        int rr = m * N_TOT + n_base + r0;
        g_idx[rr] = bi0; g_rowdist[rr] = b1v0;
        if (b2v0 - b1v0 <= MARGIN) { int p = atomicAdd(&g_fbcnt[m], 1); g_fblist[m][p] = n_base + r0; }
        rr += 8;
        g_idx[rr] = bi1; g_rowdist[rr] = b1v1;
        if (b2v1 - b1v1 <= MARGIN) { int p = atomicAdd(&g_fbcnt[m], 1); g_fblist[m][p] = n_base + r0 + 8; }
    }
}

// ---------------------------------------------------------------------------
// Exact fp32 fallback for flagged rows: reference-style quantized compare
// fl(fl(zn+en) - 2*dot), lowest-index ties (R5-proven semantics).
// Stores rowdist in dist' convention (minus zn).
// ---------------------------------------------------------------------------
__global__ __launch_bounds__(256)
void vq_fallback_kernel(const float* __restrict__ z, const float* __restrict__ cb)
{
    __shared__ float zr[8][64];
    __shared__ float zns[8];
    __shared__ int   srow[8];
    __shared__ float rbv[8][256];
    __shared__ int   rbi[8][256];
    const int tid = threadIdx.x;
    const int m = blockIdx.y;
    const int cnt = g_fbcnt[m];

    for (int base = blockIdx.x * 8; base < cnt; base += gridDim.x * 8) {
        int nrows = min(8, cnt - base);
        if (tid < 8) srow[tid] = g_fblist[m][(tid < nrows) ? base + tid : base];
        __syncthreads();
        for (int t = tid; t < 8 * 64; t += 256) {
            int j = t >> 6, d = t & 63, n = srow[j];
            zr[j][d] = z[(size_t)((n >> 10) * C_TOT + m * E_DIM + d) * HW + (n & 1023)];
        }
        __syncthreads();
        if (tid < 8) {
            float s = 0.f;
            for (int d = 0; d < 64; d++) s = __fmaf_rn(zr[tid][d], zr[tid][d], s);
            zns[tid] = s;
        }
        __syncthreads();

        float b1[8]; int bi[8];
        #pragma unroll
        for (int j = 0; j < 8; j++) { b1[j] = 3.4e38f; bi[j] = 0; }

        for (int kq = 0; kq < 4; kq++) {
            int c = tid + kq * 256;                       // ascending per thread
            const float4* cr = reinterpret_cast<const float4*>(
                cb + ((size_t)m * NE + c) * E_DIM);
            float en = 0.f; float dot[8];
            #pragma unroll
            for (int j = 0; j < 8; j++) dot[j] = 0.f;
            #pragma unroll
            for (int q = 0; q < 16; q++) {
                float4 e = cr[q];
                en = __fmaf_rn(e.x, e.x, __fmaf_rn(e.y, e.y,
                     __fmaf_rn(e.z, e.z, __fmaf_rn(e.w, e.w, en))));
                #pragma unroll
                for (int j = 0; j < 8; j++) {
                    dot[j] = __fmaf_rn(zr[j][q * 4 + 0], e.x, dot[j]);
                    dot[j] = __fmaf_rn(zr[j][q * 4 + 1], e.y, dot[j]);
                    dot[j] = __fmaf_rn(zr[j][q * 4 + 2], e.z, dot[j]);
                    dot[j] = __fmaf_rn(zr[j][q * 4 + 3], e.w, dot[j]);
                }
            }
            #pragma unroll
            for (int j = 0; j < 8; j++) {
                float dist = __fmaf_rn(-2.f, dot[j], __fadd_rn(zns[j], en));
                if (dist < b1[j]) { b1[j] = dist; bi[j] = c; }
            }
        }
        #pragma unroll
        for (int j = 0; j < 8; j++) { rbv[j][tid] = b1[j]; rbi[j][tid] = bi[j]; }
        __syncthreads();

        int wj = tid >> 5, lane = tid & 31;
        {
            float v = rbv[wj][lane]; int i0 = rbi[wj][lane];
            #pragma unroll
            for (int k = 1; k < 8; k++) {
                float ov = rbv[wj][lane + 32 * k]; int oi = rbi[wj][lane + 32 * k];
                if (ov < v || (ov == v && oi < i0)) { v = ov; i0 = oi; }
            }
            #pragma unroll
            for (int off = 16; off >= 1; off >>= 1) {
                float ov = __shfl_xor_sync(0xffffffffu, v, off);
                int   oi = __shfl_xor_sync(0xffffffffu, i0, off);
                if (ov < v || (ov == v && oi < i0)) { v = ov; i0 = oi; }
            }
            if (lane == 0 && wj < nrows) {
                int n = srow[wj];
                g_idx[m * N_TOT + n] = i0;
                g_rowdist[m * N_TOT + n] = v - zns[wj];   // dist' convention
            }
        }
        __syncthreads();
    }
}

// ---------------------------------------------------------------------------
// Scatter: gather chosen codes, straight-through rounding bit-exact
// (zq_st = fl(zf + fl(zq - zf))), scatter to NCHW, histogram,
// + deterministic per-block sum of z^2 (loss reassembly).
// ---------------------------------------------------------------------------
#define ZS_STRIDE 68
__global__ __launch_bounds__(256)
void vq_scatter_kernel(const float* __restrict__ z, const float* __restrict__ cb,
                       float* __restrict__ out)
{
    __shared__ float cs[TM][ZS_STRIDE];
    __shared__ int   sidx[TM];
    __shared__ float red[256];
    const int tid = threadIdx.x;
    const int m = blockIdx.y, tile = blockIdx.x;
    const int n_base = tile * TM, b = n_base >> 10, hw0 = n_base & 1023;

    if (tid < TM) {
        int v = g_idx[m * N_TOT + n_base + tid];
        sidx[tid] = v;
        atomicAdd(&g_bins[v], 1);
    }
    __syncthreads();
    const float4* cb4 = reinterpret_cast<const float4*>(cb + (size_t)m * NE * E_DIM);
    for (int idx4 = tid; idx4 < TM * 16; idx4 += 256) {
        int r = idx4 >> 4, d4 = idx4 & 15;
        float4 v = cb4[sidx[r] * 16 + d4];
        *reinterpret_cast<float4*>(&cs[r][d4 * 4]) = v;
    }
    __syncthreads();
    const float* zsrc = z   + (size_t)(b * C_TOT + m * E_DIM) * HW + hw0;
    float*       dst  = out + (size_t)(b * C_TOT + m * E_DIM) * HW + hw0;
    float zs = 0.f;
    for (int idx = tid; idx < E_DIM * TM; idx += 256) {
        int d = idx >> 7, nl = idx & 127;
        size_t off = (size_t)d * HW + nl;
        float zv = zsrc[off];
        zs += zv * zv;
        float t  = __fsub_rn(cs[nl][d], zv);
        dst[off] = __fadd_rn(zv, t);
    }
    red[tid] = zs;
    __syncthreads();
    for (int s = 128; s >= 1; s >>= 1) {
        if (tid < s) red[tid] += red[tid + s];
        __syncthreads();
    }
    if (tid == 0) g_zpart[m * 128 + tile] = red[0];
}

// ---------------------------------------------------------------------------
// Final: deterministic loss = (sum dist' + sum z^2) * 1.25/(N*64),
// + idx/bin dtype conversion.
// ---------------------------------------------------------------------------
__global__ __launch_bounds__(256)
void vq_final_kernel(float* __restrict__ out)
{
    if (blockIdx.x == 0) {
        __shared__ float part[256];
        int tid = threadIdx.x;
        float s = 0.f;
        for (int i = tid; i < M_SUB * N_TOT; i += 256) s += g_rowdist[i];
        for (int i = tid; i < 1024; i += 256) s += g_zpart[i];
        part[tid] = s;
        __syncthreads();
        if (tid == 0) {
            float t = 0.f;
            for (int q = 0; q < 256; q++) t += part[q];
            out[OUT_LOSS] = t * (1.25f / (float)(N_TOT * E_DIM));
        }
    } else {
        int off = (blockIdx.x - 1) * 256 + threadIdx.x;
        if (off < M_SUB * N_TOT) {
            out[OUT_IDX + off] = (float)g_idx[off];
        } else {
            int bo = off - M_SUB * N_TOT;
            if (bo < NE) out[OUT_BIN + bo] = (float)g_bins[bo];
        }
    }
}

// ---------------------------------------------------------------------------
extern "C" void kernel_launch(void* const* d_in, const int* in_sizes, int n_in,
                              void* d_out, int out_size)
{
    const float* z  = (const float*)d_in[0];
    const float* cb = (const float*)d_in[1];
    float* out = (float*)d_out;

    cudaFuncSetAttribute(vq_tensor_kernel,
                         cudaFuncAttributeMaxDynamicSharedMemorySize, SMEM_BYTES);

    vq_init_kernel<<<5, 256>>>();
    vq_precompute_kernel<<<32, 256>>>(cb);

    dim3 gridT(N_TOT / TM, M_SUB);            // 128 x 8
    vq_tensor_kernel<<<gridT, 256, SMEM_BYTES>>>(z);

    dim3 gridF(32, M_SUB);
    vq_fallback_kernel<<<gridF, 256>>>(z, cb);

    dim3 gridS(N_TOT / TM, M_SUB);
    vq_scatter_kernel<<<gridS, 256>>>(z, cb, out);

    int conv_elems = M_SUB * N_TOT + NE;
    int gridC = 1 + (conv_elems + 255) / 256;
    vq_final_kernel<<<gridC, 256>>>(out);
}

// round 14
// speedup vs baseline: 2.0439x; 1.2961x over previous
#include <cuda_runtime.h>
#include <cuda_bf16.h>
#include <cstdint>

// Problem constants
#define BS      16
#define C_TOT   512
#define HW      1024
#define N_TOT   16384
#define M_SUB   8
#define NE      1024
#define E_DIM   64

// Tiling
#define TM      128            // z rows per CTA
#define KC      64             // codes per chunk (tensor kernel)
#define NCH     (NE / KC)      // 16
#define MARGIN  5e-5f          // >= worst-case cross-scale ordering discrepancy (~3.1e-5)

// Output layout (float32, tuple-concatenated)
#define OUT_LOSS 8388608
#define OUT_IDX  8388609
#define OUT_BIN  (OUT_IDX + M_SUB * N_TOT)

// Scratch (static; no cudaMalloc allowed)
__device__ int   g_idx[M_SUB * N_TOT];
__device__ float g_rowdist[M_SUB * N_TOT];       // dist' = en - 2*dot (no zn)
__device__ int   g_bins[NE];
__device__ int   g_fbcnt[M_SUB];
__device__ int   g_fblist[M_SUB][N_TOT];
__device__ unsigned long long g_fbkey[M_SUB * N_TOT];
__device__ float g_zpart[1024];                  // per-(m,tile) sum of z^2
// pre-split codebook: [m*NE + code][split(2)][32 words of bf16x2]
__device__ __align__(16) uint32_t g_cbsplit[M_SUB * NE * 64];
__device__ __align__(16) float    g_en[M_SUB * NE];

// ---- tensor-kernel smem word map (u32 units) ----
// zsh (A staging, 2 splits x 128 rows x 36w) occupies words 0..9215;
// B buf1 (2 splits x 64 codes x 36w = 4608w) OVERLAYS words 0..4607 (zsh is
// dead after A-frags are loaded into registers, before buf1's first fill).
// B buf0 at 9216..13823 (disjoint from zsh: filled during A staging).
#define W_B1  0
#define W_B0  9216
#define W_EN  13824            // [2 buf][64] floats
#define SMEM_WORDS 13952
#define SMEM_BYTES (SMEM_WORDS * 4)   // 55808 B

__device__ __forceinline__ void cp_async16(uint32_t saddr, const void* gptr) {
    asm volatile("cp.async.cg.shared.global [%0], [%1], 16;" :: "r"(saddr), "l"(gptr));
}
#define CP_COMMIT() asm volatile("cp.async.commit_group;")
#define CP_WAIT(n)  asm volatile("cp.async.wait_group %0;" :: "n"(n))

__device__ __forceinline__ void mma_bf16(float* c, const uint32_t* a,
                                         uint32_t b0, uint32_t b1) {
    asm volatile(
        "mma.sync.aligned.m16n8k16.row.col.f32.bf16.bf16.f32 "
        "{%0,%1,%2,%3}, {%4,%5,%6,%7}, {%8,%9}, {%0,%1,%2,%3};"
        : "+f"(c[0]), "+f"(c[1]), "+f"(c[2]), "+f"(c[3])
        : "r"(a[0]), "r"(a[1]), "r"(a[2]), "r"(a[3]), "r"(b0), "r"(b1));
}

__device__ __forceinline__ uint32_t pack2(float a, float b) {
    __nv_bfloat162 t = __floats2bfloat162_rn(a, b);
    return *reinterpret_cast<uint32_t*>(&t);
}
__device__ __forceinline__ void split1(float v, float& hi, float& lo) {
    __nv_bfloat16 h = __float2bfloat16_rn(v);
    hi = __bfloat162float(h);
    lo = v - hi;                       // exact in fp32
}

// ---------------------------------------------------------------------------
__global__ void vq_init_kernel() {
    int t = blockIdx.x * 256 + threadIdx.x;
    if (t < NE) g_bins[t] = 0;
    if (t >= NE && t < NE + M_SUB) g_fbcnt[t - NE] = 0;
}

// ---------------------------------------------------------------------------
// Precompute: split codebook to bf16 hi/lo planes (mma-ready layout) + ||e||^2.
// ---------------------------------------------------------------------------
__global__ __launch_bounds__(256)
void vq_precompute_kernel(const float* __restrict__ cb)
{
    int t = blockIdx.x * 256 + threadIdx.x;      // 8192 codes total
    if (t >= M_SUB * NE) return;
    const float4* src = reinterpret_cast<const float4*>(cb + (size_t)t * E_DIM);
    uint32_t* dst = g_cbsplit + (size_t)t * 64;  // [split][32w]
    float en = 0.f;
    #pragma unroll
    for (int q = 0; q < 16; q++) {
        float4 v = src[q];
        en += v.x * v.x + v.y * v.y + v.z * v.z + v.w * v.w;
        float hx, lx, hy, ly, hz, lz, hw_, lw_;
        split1(v.x, hx, lx); split1(v.y, hy, ly);
        split1(v.z, hz, lz); split1(v.w, hw_, lw_);
        dst[q * 2]          = pack2(hx, hy);
        dst[q * 2 + 1]      = pack2(hz, hw_);
        dst[32 + q * 2]     = pack2(lx, ly);
        dst[32 + q * 2 + 1] = pack2(lz, lw_);
    }
    g_en[t] = en;
}

// ---------------------------------------------------------------------------
// Tensor kernel: bf16-split mma.sync (3 products), per-row argmin on
// dist' = en - 2*dot (row-constant zn dropped; ordering preserved within
// MARGIN, flagged rows re-solved exactly). Product-major MMA bursts give 8
// independent accumulator chains. B panels arrive pre-split via cp.async.
// Per-thread code order ascending + strict < => lowest-index tie-break.
// ---------------------------------------------------------------------------
__global__ __launch_bounds__(256, 2)
void vq_tensor_kernel(const float* __restrict__ z)
{
    extern __shared__ __align__(16) uint32_t sm[];
    float* smf = reinterpret_cast<float*>(sm);
    __nv_bfloat16* smh = reinterpret_cast<__nv_bfloat16*>(sm);

    const int tid = threadIdx.x;
    const int w = tid >> 5, lane = tid & 31, g = lane >> 2, tg = lane & 3;
    const int m = blockIdx.y, tile = blockIdx.x;
    const int n_base = tile * TM, b = n_base >> 10, hw0 = n_base & 1023;

    const uint32_t sbase = (uint32_t)__cvta_generic_to_shared(sm);

    // prefetch one chunk's pre-split panels + en into buf
    auto prefetch = [&](int ch, int buf) {
        const uint32_t bw = buf ? W_B1 : W_B0;
        const uint32_t* src = g_cbsplit + ((size_t)m * NE + ch * KC) * 64;
        #pragma unroll
        for (int q = 0; q < 4; q++) {
            int idx = q * 256 + tid;                 // 0..1023
            int split = idx >> 9, code = (idx >> 3) & 63, p = idx & 7;
            uint32_t dw = bw + split * 2304 + code * 36 + p * 4;
            cp_async16(sbase + dw * 4, src + (size_t)code * 64 + split * 32 + p * 4);
        }
        if (tid < 16)
            cp_async16(sbase + (W_EN + buf * 64 + tid * 4) * 4,
                       g_en + m * NE + ch * KC + tid * 4);
        CP_COMMIT();
    };

    // chunk 0 -> buf0 (disjoint from A staging area)
    prefetch(0, 0);

    // stage A: split z rows into bf16 hi/lo planes at words 0..9215
    {
        const int row = tid & 127, h = tid >> 7;
        const float* zsrc = z + (size_t)(b * C_TOT + m * E_DIM) * HW + hw0;
        #pragma unroll
        for (int i = 0; i < 32; i++) {
            int d = h + 2 * i;
            float v = zsrc[(size_t)d * HW + row];
            float hi, lo; split1(v, hi, lo);
            smh[row * 72 + d]        = __float2bfloat16_rn(hi);
            smh[9216 + row * 72 + d] = __float2bfloat16_rn(lo);
        }
    }
    __syncthreads();

    // A fragments -> registers (reused for all 16 chunks)
    const int r0 = w * 16 + g;
    uint32_t af[2][4][4];
    #pragma unroll
    for (int s = 0; s < 2; s++)
        #pragma unroll
        for (int ks = 0; ks < 4; ks++) {
            int base = s * 4608 + ks * 8 + tg;
            af[s][ks][0] = sm[base + r0 * 36];
            af[s][ks][1] = sm[base + (r0 + 8) * 36];
            af[s][ks][2] = sm[base + r0 * 36 + 4];
            af[s][ks][3] = sm[base + (r0 + 8) * 36 + 4];
        }
    __syncthreads();          // zsh fully consumed; buf1 region now writable

    prefetch(1, 1);

    float b1v0 = 3.4e38f, b2v0 = 3.4e38f, b1v1 = 3.4e38f, b2v1 = 3.4e38f;
    int   bi0 = 0, bi1 = 0;
    const int boff = g * 36 + tg;

    for (int ch = 0; ch < NCH; ch++) {
        const int buf = ch & 1;
        const uint32_t bw = buf ? W_B1 : W_B0;
        if (ch == NCH - 1) { CP_WAIT(0); } else { CP_WAIT(1); }
        __syncthreads();                         // panels[buf] + en[buf] visible

        float acc[8][4];
        #pragma unroll
        for (int nt = 0; nt < 8; nt++)
            acc[nt][0] = acc[nt][1] = acc[nt][2] = acc[nt][3] = 0.f;

        #pragma unroll
        for (int ks = 0; ks < 4; ks++) {
            const int kb = bw + ks * 8 + boff;
            uint32_t bh[8][2];
            #pragma unroll
            for (int nt = 0; nt < 8; nt++) {
                bh[nt][0] = sm[kb + nt * 288];
                bh[nt][1] = sm[kb + nt * 288 + 4];
            }
            #pragma unroll
            for (int nt = 0; nt < 8; nt++)       // Ah*Bh: 8 independent
                mma_bf16(acc[nt], af[0][ks], bh[nt][0], bh[nt][1]);
            #pragma unroll
            for (int nt = 0; nt < 8; nt++)       // Al*Bh: reuse frags
                mma_bf16(acc[nt], af[1][ks], bh[nt][0], bh[nt][1]);
            uint32_t bl[8][2];
            #pragma unroll
            for (int nt = 0; nt < 8; nt++) {
                bl[nt][0] = sm[kb + 2304 + nt * 288];
                bl[nt][1] = sm[kb + 2304 + nt * 288 + 4];
            }
            #pragma unroll
            for (int nt = 0; nt < 8; nt++)       // Ah*Bl
                mma_bf16(acc[nt], af[0][ks], bl[nt][0], bl[nt][1]);
        }

        // epilogue: dist' = en - 2*dot; track (min1, min2, idx) per row
        const float* enp = smf + W_EN + buf * 64;
        #pragma unroll
        for (int nt = 0; nt < 8; nt++) {
            float en0 = enp[nt * 8 + tg * 2];
            float en1 = enp[nt * 8 + tg * 2 + 1];
            int k0 = ch * 64 + nt * 8 + tg * 2;
            float d00 = __fmaf_rn(-2.f, acc[nt][0], en0);
            float d01 = __fmaf_rn(-2.f, acc[nt][1], en1);
            float d10 = __fmaf_rn(-2.f, acc[nt][2], en0);
            float d11 = __fmaf_rn(-2.f, acc[nt][3], en1);
            if (d00 < b1v0) { b2v0 = b1v0; b1v0 = d00; bi0 = k0; }     else if (d00 < b2v0) b2v0 = d00;
            if (d01 < b1v0) { b2v0 = b1v0; b1v0 = d01; bi0 = k0 + 1; } else if (d01 < b2v0) b2v0 = d01;
            if (d10 < b1v1) { b2v1 = b1v1; b1v1 = d10; bi1 = k0; }     else if (d10 < b2v1) b2v1 = d10;
            if (d11 < b1v1) { b2v1 = b1v1; b1v1 = d11; bi1 = k0 + 1; } else if (d11 < b2v1) b2v1 = d11;
        }
        __syncthreads();                         // all reads of buf done
        if (ch + 2 < NCH) prefetch(ch + 2, buf);
    }

    // quad reduce (lanes tg 0..3 share rows r0 / r0+8); keeps true 2nd-min
    #pragma unroll
    for (int off = 1; off <= 2; off <<= 1) {
        float o1 = __shfl_xor_sync(0xffffffffu, b1v0, off);
        float o2 = __shfl_xor_sync(0xffffffffu, b2v0, off);
        int   oi = __shfl_xor_sync(0xffffffffu, bi0, off);
        if (o1 < b1v0 || (o1 == b1v0 && oi < bi0)) { b2v0 = fminf(b1v0, o2); b1v0 = o1; bi0 = oi; }
        else b2v0 = fminf(b2v0, o1);
        float p1 = __shfl_xor_sync(0xffffffffu, b1v1, off);
        float p2 = __shfl_xor_sync(0xffffffffu, b2v1, off);
        int   pi = __shfl_xor_sync(0xffffffffu, bi1, off);
        if (p1 < b1v1 || (p1 == b1v1 && pi < bi1)) { b2v1 = fminf(b1v1, p2); b1v1 = p1; bi1 = pi; }
        else b2v1 = fminf(b2v1, p1);
    }

    if (tg == 0) {
        int rr = m * N_TOT + n_base + r0;
        g_idx[rr] = bi0; g_rowdist[rr] = b1v0;
        if (b2v0 - b1v0 <= MARGIN) {
            g_fbkey[rr] = ~0ull;
            int p = atomicAdd(&g_fbcnt[m], 1); g_fblist[m][p] = n_base + r0;
        }
        rr += 8;
        g_idx[rr] = bi1; g_rowdist[rr] = b1v1;
        if (b2v1 - b1v1 <= MARGIN) {
            g_fbkey[rr] = ~0ull;
            int p = atomicAdd(&g_fbcnt[m], 1); g_fblist[m][p] = n_base + r0 + 8;
        }
    }
}

// ---------------------------------------------------------------------------
// Exact fallback, chunk-parallel: block = (code-chunk cx, row-tile by, m).
// Each block stages 128 codes in smem; each thread owns one flagged row
// (z in registers), computes the reference-style quantized dist
// fl(fl(zn+en) - 2*dot) over the chunk with ascending-k strict < (lowest
// index), and atomicMin's a (dist_bits<<32 | idx) key. dist > 0 so float
// bits are order-monotone; zn is computed by an identical code path in
// every block => bit-identical => cross-block compares are exact.
// ---------------------------------------------------------------------------
__global__ __launch_bounds__(128)
void vq_fallback_kernel(const float* __restrict__ z, const float* __restrict__ cb)
{
    __shared__ float sc[128][64];
    __shared__ float sen[128];
    const int tid = threadIdx.x;
    const int cx = blockIdx.x;            // code chunk 0..7
    const int m  = blockIdx.z;
    const int cnt = g_fbcnt[m];
    if ((int)blockIdx.y * 128 >= cnt) return;

    // stage 128 codes (coalesced float4)
    const float4* src = reinterpret_cast<const float4*>(
        cb + ((size_t)m * NE + cx * 128) * E_DIM);
    for (int i = tid; i < 128 * 16; i += 128) {
        int code = i >> 4, q = i & 15;
        *reinterpret_cast<float4*>(&sc[code][q * 4]) = src[(size_t)code * 16 + q];
    }
    __syncthreads();
    {
        float s = 0.f;
        const float* cr = sc[tid];
        #pragma unroll
        for (int d = 0; d < 64; d++) s = __fmaf_rn(cr[d], cr[d], s);
        sen[tid] = s;
    }
    __syncthreads();

    for (int t0 = blockIdx.y * 128; t0 < cnt; t0 += 16 * 128) {
        int i = t0 + tid;
        if (i >= cnt) continue;
        int n = g_fblist[m][i];
        int r = m * N_TOT + n;
        int b = n >> 10, hw = n & 1023;
        const float* zp = z + (size_t)(b * C_TOT + m * E_DIM) * HW + hw;
        float zr[64];
        #pragma unroll
        for (int d = 0; d < 64; d++) zr[d] = zp[(size_t)d * HW];
        float zn = 0.f;
        #pragma unroll
        for (int d = 0; d < 64; d++) zn = __fmaf_rn(zr[d], zr[d], zn);

        float bv = 3.4e38f; int bc = 0;
        for (int c = 0; c < 128; c++) {              // ascending => lowest idx
            const float4* cr4 = reinterpret_cast<const float4*>(sc[c]);
            float d0 = 0.f, d1 = 0.f, d2 = 0.f, d3 = 0.f;
            #pragma unroll
            for (int q = 0; q < 16; q++) {
                float4 e = cr4[q];
                d0 = __fmaf_rn(zr[q * 4 + 0], e.x, d0);
                d1 = __fmaf_rn(zr[q * 4 + 1], e.y, d1);
                d2 = __fmaf_rn(zr[q * 4 + 2], e.z, d2);
                d3 = __fmaf_rn(zr[q * 4 + 3], e.w, d3);
            }
            float dot  = __fadd_rn(__fadd_rn(d0, d1), __fadd_rn(d2, d3));
            float dist = __fmaf_rn(-2.f, dot, __fadd_rn(zn, sen[c]));
            if (dist < bv) { bv = dist; bc = c; }
        }
        unsigned long long key =
            ((unsigned long long)__float_as_uint(bv) << 32)
            | (unsigned)(cx * 128 + bc);
        atomicMin(&g_fbkey[r], key);
    }
}

// ---------------------------------------------------------------------------
// Apply: decode winning keys into g_idx / g_rowdist (dist' convention).
// ---------------------------------------------------------------------------
__global__ __launch_bounds__(256)
void vq_apply_kernel(const float* __restrict__ z)
{
    const int m = blockIdx.y;
    const int cnt = g_fbcnt[m];
    for (int i = blockIdx.x * 256 + threadIdx.x; i < cnt; i += gridDim.x * 256) {
        int n = g_fblist[m][i];
        int r = m * N_TOT + n;
        unsigned long long key = g_fbkey[r];
        int   idx  = (int)(key & 0xFFFFFFFFull);
        float dist = __uint_as_float((unsigned)(key >> 32));
        int b = n >> 10, hw = n & 1023;
        const float* zp = z + (size_t)(b * C_TOT + m * E_DIM) * HW + hw;
        float zn = 0.f;
        #pragma unroll
        for (int d = 0; d < 64; d++) {
            float v = zp[(size_t)d * HW];
            zn = __fmaf_rn(v, v, zn);
        }
        g_idx[r] = idx;
        g_rowdist[r] = dist - zn;      // dist' convention
    }
}

// ---------------------------------------------------------------------------
// Scatter: gather chosen codes, straight-through rounding bit-exact
// (zq_st = fl(zf + fl(zq - zf))), scatter to NCHW, histogram,
// + deterministic per-block sum of z^2 (loss reassembly).
// ---------------------------------------------------------------------------
#define ZS_STRIDE 68
__global__ __launch_bounds__(256)
void vq_scatter_kernel(const float* __restrict__ z, const float* __restrict__ cb,
                       float* __restrict__ out)
{
    __shared__ float cs[TM][ZS_STRIDE];
    __shared__ int   sidx[TM];
    __shared__ float red[256];
    const int tid = threadIdx.x;
    const int m = blockIdx.y, tile = blockIdx.x;
    const int n_base = tile * TM, b = n_base >> 10, hw0 = n_base & 1023;

    if (tid < TM) {
        int v = g_idx[m * N_TOT + n_base + tid];
        sidx[tid] = v;
        atomicAdd(&g_bins[v], 1);
    }
    __syncthreads();
    const float4* cb4 = reinterpret_cast<const float4*>(cb + (size_t)m * NE * E_DIM);
    for (int idx4 = tid; idx4 < TM * 16; idx4 += 256) {
        int r = idx4 >> 4, d4 = idx4 & 15;
        float4 v = cb4[sidx[r] * 16 + d4];
        *reinterpret_cast<float4*>(&cs[r][d4 * 4]) = v;
    }
    __syncthreads();
    const float* zsrc = z   + (size_t)(b * C_TOT + m * E_DIM) * HW + hw0;
    float*       dst  = out + (size_t)(b * C_TOT + m * E_DIM) * HW + hw0;
    float zs = 0.f;
    for (int idx = tid; idx < E_DIM * TM; idx += 256) {
        int d = idx >> 7, nl = idx & 127;
        size_t off = (size_t)d * HW + nl;
        float zv = zsrc[off];
        zs += zv * zv;
        float t  = __fsub_rn(cs[nl][d], zv);
        dst[off] = __fadd_rn(zv, t);
    }
    red[tid] = zs;
    __syncthreads();
    for (int s = 128; s >= 1; s >>= 1) {
        if (tid < s) red[tid] += red[tid + s];
        __syncthreads();
    }
    if (tid == 0) g_zpart[m * 128 + tile] = red[0];
}

// ---------------------------------------------------------------------------
// Final: deterministic loss = (sum dist' + sum z^2) * 1.25/(N*64),
// + idx/bin dtype conversion.
// ---------------------------------------------------------------------------
__global__ __launch_bounds__(256)
void vq_final_kernel(float* __restrict__ out)
{
    if (blockIdx.x == 0) {
        __shared__ float part[256];
        int tid = threadIdx.x;
        float s = 0.f;
        for (int i = tid; i < M_SUB * N_TOT; i += 256) s += g_rowdist[i];
        for (int i = tid; i < 1024; i += 256) s += g_zpart[i];
        part[tid] = s;
        __syncthreads();
        if (tid == 0) {
            float t = 0.f;
            for (int q = 0; q < 256; q++) t += part[q];
            out[OUT_LOSS] = t * (1.25f / (float)(N_TOT * E_DIM));
        }
    } else {
        int off = (blockIdx.x - 1) * 256 + threadIdx.x;
        if (off < M_SUB * N_TOT) {
            out[OUT_IDX + off] = (float)g_idx[off];
        } else {
            int bo = off - M_SUB * N_TOT;
            if (bo < NE) out[OUT_BIN + bo] = (float)g_bins[bo];
        }
    }
}

// ---------------------------------------------------------------------------
extern "C" void kernel_launch(void* const* d_in, const int* in_sizes, int n_in,
                              void* d_out, int out_size)
{
    const float* z  = (const float*)d_in[0];
    const float* cb = (const float*)d_in[1];
    float* out = (float*)d_out;

    cudaFuncSetAttribute(vq_tensor_kernel,
                         cudaFuncAttributeMaxDynamicSharedMemorySize, SMEM_BYTES);

    vq_init_kernel<<<5, 256>>>();
    vq_precompute_kernel<<<32, 256>>>(cb);

    dim3 gridT(N_TOT / TM, M_SUB);            // 128 x 8
    vq_tensor_kernel<<<gridT, 256, SMEM_BYTES>>>(z);

    dim3 gridF(8, 16, M_SUB);                 // chunk x row-tile x m
    vq_fallback_kernel<<<gridF, 128>>>(z, cb);

    dim3 gridA(4, M_SUB);
    vq_apply_kernel<<<gridA, 256>>>(z);

    dim3 gridS(N_TOT / TM, M_SUB);
    vq_scatter_kernel<<<gridS, 256>>>(z, cb, out);

    int conv_elems = M_SUB * N_TOT + NE;
    int gridC = 1 + (conv_elems + 255) / 256;
    vq_final_kernel<<<gridC, 256>>>(out);
}

// round 15
// speedup vs baseline: 2.2810x; 1.1160x over previous
#include <cuda_runtime.h>
#include <cuda_bf16.h>
#include <cstdint>

// Problem constants
#define BS      16
#define C_TOT   512
#define HW      1024
#define N_TOT   16384
#define M_SUB   8
#define NE      1024
#define E_DIM   64

// Tiling
#define TM      128            // z rows per CTA
#define KC      64             // codes per chunk (tensor kernel)
#define NCH     (NE / KC)      // 16
#define MARGIN  5e-5f          // >= worst-case cross-scale ordering discrepancy (~3.1e-5)

// Output layout (float32, tuple-concatenated)
#define OUT_LOSS 8388608
#define OUT_IDX  8388609
#define OUT_BIN  (OUT_IDX + M_SUB * N_TOT)

// Scratch (static; no cudaMalloc allowed)
__device__ int   g_idx[M_SUB * N_TOT];
__device__ float g_rowdist[M_SUB * N_TOT];       // dist' = en - 2*dot (no zn)
__device__ int   g_bins[NE];
__device__ int   g_fbcnt[M_SUB];
__device__ int   g_fblist[M_SUB][N_TOT];
__device__ unsigned long long g_fbkey[M_SUB * N_TOT];
__device__ float g_zpart[1024];                  // per-(m,tile): sum z^2 + sum dist'
// pre-split codebook: [m*NE + code][split(2)][32 words of bf16x2]
__device__ __align__(16) uint32_t g_cbsplit[M_SUB * NE * 64];
__device__ __align__(16) float    g_en[M_SUB * NE];

// ---- tensor-kernel smem word map (u32 units) ----
#define W_B1  0
#define W_B0  9216
#define W_EN  13824            // [2 buf][64] floats
#define SMEM_WORDS 13952
#define SMEM_BYTES (SMEM_WORDS * 4)   // 55808 B

__device__ __forceinline__ void cp_async16(uint32_t saddr, const void* gptr) {
    asm volatile("cp.async.cg.shared.global [%0], [%1], 16;" :: "r"(saddr), "l"(gptr));
}
#define CP_COMMIT() asm volatile("cp.async.commit_group;")
#define CP_WAIT(n)  asm volatile("cp.async.wait_group %0;" :: "n"(n))

__device__ __forceinline__ void mma_bf16(float* c, const uint32_t* a,
                                         uint32_t b0, uint32_t b1) {
    asm volatile(
        "mma.sync.aligned.m16n8k16.row.col.f32.bf16.bf16.f32 "
        "{%0,%1,%2,%3}, {%4,%5,%6,%7}, {%8,%9}, {%0,%1,%2,%3};"
        : "+f"(c[0]), "+f"(c[1]), "+f"(c[2]), "+f"(c[3])
        : "r"(a[0]), "r"(a[1]), "r"(a[2]), "r"(a[3]), "r"(b0), "r"(b1));
}

__device__ __forceinline__ uint32_t pack2(float a, float b) {
    __nv_bfloat162 t = __floats2bfloat162_rn(a, b);
    return *reinterpret_cast<uint32_t*>(&t);
}
__device__ __forceinline__ void split1(float v, float& hi, float& lo) {
    __nv_bfloat16 h = __float2bfloat16_rn(v);
    hi = __bfloat162float(h);
    lo = v - hi;                       // exact in fp32
}

// ---------------------------------------------------------------------------
__global__ void vq_init_kernel() {
    int t = blockIdx.x * 256 + threadIdx.x;
    if (t < NE) g_bins[t] = 0;
    if (t >= NE && t < NE + M_SUB) g_fbcnt[t - NE] = 0;
}

// ---------------------------------------------------------------------------
// Precompute: split codebook to bf16 hi/lo planes (mma-ready layout) + ||e||^2.
// ---------------------------------------------------------------------------
__global__ __launch_bounds__(256)
void vq_precompute_kernel(const float* __restrict__ cb)
{
    int t = blockIdx.x * 256 + threadIdx.x;      // 8192 codes total
    if (t >= M_SUB * NE) return;
    const float4* src = reinterpret_cast<const float4*>(cb + (size_t)t * E_DIM);
    uint32_t* dst = g_cbsplit + (size_t)t * 64;  // [split][32w]
    float en = 0.f;
    #pragma unroll
    for (int q = 0; q < 16; q++) {
        float4 v = src[q];
        en += v.x * v.x + v.y * v.y + v.z * v.z + v.w * v.w;
        float hx, lx, hy, ly, hz, lz, hw_, lw_;
        split1(v.x, hx, lx); split1(v.y, hy, ly);
        split1(v.z, hz, lz); split1(v.w, hw_, lw_);
        dst[q * 2]          = pack2(hx, hy);
        dst[q * 2 + 1]      = pack2(hz, hw_);
        dst[32 + q * 2]     = pack2(lx, ly);
        dst[32 + q * 2 + 1] = pack2(lz, lw_);
    }
    g_en[t] = en;
}

// ---------------------------------------------------------------------------
// Tensor kernel (unchanged from R14-passing version): bf16-split mma.sync
// (3 products), per-row argmin on dist' = en - 2*dot with second-min margin.
// ---------------------------------------------------------------------------
__global__ __launch_bounds__(256, 2)
void vq_tensor_kernel(const float* __restrict__ z)
{
    extern __shared__ __align__(16) uint32_t sm[];
    float* smf = reinterpret_cast<float*>(sm);
    __nv_bfloat16* smh = reinterpret_cast<__nv_bfloat16*>(sm);

    const int tid = threadIdx.x;
    const int w = tid >> 5, lane = tid & 31, g = lane >> 2, tg = lane & 3;
    const int m = blockIdx.y, tile = blockIdx.x;
    const int n_base = tile * TM, b = n_base >> 10, hw0 = n_base & 1023;

    const uint32_t sbase = (uint32_t)__cvta_generic_to_shared(sm);

    auto prefetch = [&](int ch, int buf) {
        const uint32_t bw = buf ? W_B1 : W_B0;
        const uint32_t* src = g_cbsplit + ((size_t)m * NE + ch * KC) * 64;
        #pragma unroll
        for (int q = 0; q < 4; q++) {
            int idx = q * 256 + tid;                 // 0..1023
            int split = idx >> 9, code = (idx >> 3) & 63, p = idx & 7;
            uint32_t dw = bw + split * 2304 + code * 36 + p * 4;
            cp_async16(sbase + dw * 4, src + (size_t)code * 64 + split * 32 + p * 4);
        }
        if (tid < 16)
            cp_async16(sbase + (W_EN + buf * 64 + tid * 4) * 4,
                       g_en + m * NE + ch * KC + tid * 4);
        CP_COMMIT();
    };

    prefetch(0, 0);

    // stage A: split z rows into bf16 hi/lo planes at words 0..9215
    {
        const int row = tid & 127, h = tid >> 7;
        const float* zsrc = z + (size_t)(b * C_TOT + m * E_DIM) * HW + hw0;
        #pragma unroll
        for (int i = 0; i < 32; i++) {
            int d = h + 2 * i;
            float v = zsrc[(size_t)d * HW + row];
            float hi, lo; split1(v, hi, lo);
            smh[row * 72 + d]        = __float2bfloat16_rn(hi);
            smh[9216 + row * 72 + d] = __float2bfloat16_rn(lo);
        }
    }
    __syncthreads();

    // A fragments -> registers (reused for all 16 chunks)
    const int r0 = w * 16 + g;
    uint32_t af[2][4][4];
    #pragma unroll
    for (int s = 0; s < 2; s++)
        #pragma unroll
        for (int ks = 0; ks < 4; ks++) {
            int base = s * 4608 + ks * 8 + tg;
            af[s][ks][0] = sm[base + r0 * 36];
            af[s][ks][1] = sm[base + (r0 + 8) * 36];
            af[s][ks][2] = sm[base + r0 * 36 + 4];
            af[s][ks][3] = sm[base + (r0 + 8) * 36 + 4];
        }
    __syncthreads();          // zsh fully consumed; buf1 region now writable

    prefetch(1, 1);

    float b1v0 = 3.4e38f, b2v0 = 3.4e38f, b1v1 = 3.4e38f, b2v1 = 3.4e38f;
    int   bi0 = 0, bi1 = 0;
    const int boff = g * 36 + tg;

    for (int ch = 0; ch < NCH; ch++) {
        const int buf = ch & 1;
        const uint32_t bw = buf ? W_B1 : W_B0;
        if (ch == NCH - 1) { CP_WAIT(0); } else { CP_WAIT(1); }
        __syncthreads();

        float acc[8][4];
        #pragma unroll
        for (int nt = 0; nt < 8; nt++)
            acc[nt][0] = acc[nt][1] = acc[nt][2] = acc[nt][3] = 0.f;

        #pragma unroll
        for (int ks = 0; ks < 4; ks++) {
            const int kb = bw + ks * 8 + boff;
            uint32_t bh[8][2];
            #pragma unroll
            for (int nt = 0; nt < 8; nt++) {
                bh[nt][0] = sm[kb + nt * 288];
                bh[nt][1] = sm[kb + nt * 288 + 4];
            }
            #pragma unroll
            for (int nt = 0; nt < 8; nt++)
                mma_bf16(acc[nt], af[0][ks], bh[nt][0], bh[nt][1]);
            #pragma unroll
            for (int nt = 0; nt < 8; nt++)
                mma_bf16(acc[nt], af[1][ks], bh[nt][0], bh[nt][1]);
            uint32_t bl[8][2];
            #pragma unroll
            for (int nt = 0; nt < 8; nt++) {
                bl[nt][0] = sm[kb + 2304 + nt * 288];
                bl[nt][1] = sm[kb + 2304 + nt * 288 + 4];
            }
            #pragma unroll
            for (int nt = 0; nt < 8; nt++)
                mma_bf16(acc[nt], af[0][ks], bl[nt][0], bl[nt][1]);
        }

        const float* enp = smf + W_EN + buf * 64;
        #pragma unroll
        for (int nt = 0; nt < 8; nt++) {
            float en0 = enp[nt * 8 + tg * 2];
            float en1 = enp[nt * 8 + tg * 2 + 1];
            int k0 = ch * 64 + nt * 8 + tg * 2;
            float d00 = __fmaf_rn(-2.f, acc[nt][0], en0);
            float d01 = __fmaf_rn(-2.f, acc[nt][1], en1);
            float d10 = __fmaf_rn(-2.f, acc[nt][2], en0);
            float d11 = __fmaf_rn(-2.f, acc[nt][3], en1);
            if (d00 < b1v0) { b2v0 = b1v0; b1v0 = d00; bi0 = k0; }     else if (d00 < b2v0) b2v0 = d00;
            if (d01 < b1v0) { b2v0 = b1v0; b1v0 = d01; bi0 = k0 + 1; } else if (d01 < b2v0) b2v0 = d01;
            if (d10 < b1v1) { b2v1 = b1v1; b1v1 = d10; bi1 = k0; }     else if (d10 < b2v1) b2v1 = d10;
            if (d11 < b1v1) { b2v1 = b1v1; b1v1 = d11; bi1 = k0 + 1; } else if (d11 < b2v1) b2v1 = d11;
        }
        __syncthreads();
        if (ch + 2 < NCH) prefetch(ch + 2, buf);
    }

    #pragma unroll
    for (int off = 1; off <= 2; off <<= 1) {
        float o1 = __shfl_xor_sync(0xffffffffu, b1v0, off);
        float o2 = __shfl_xor_sync(0xffffffffu, b2v0, off);
        int   oi = __shfl_xor_sync(0xffffffffu, bi0, off);
        if (o1 < b1v0 || (o1 == b1v0 && oi < bi0)) { b2v0 = fminf(b1v0, o2); b1v0 = o1; bi0 = oi; }
        else b2v0 = fminf(b2v0, o1);
        float p1 = __shfl_xor_sync(0xffffffffu, b1v1, off);
        float p2 = __shfl_xor_sync(0xffffffffu, b2v1, off);
        int   pi = __shfl_xor_sync(0xffffffffu, bi1, off);
        if (p1 < b1v1 || (p1 == b1v1 && pi < bi1)) { b2v1 = fminf(b1v1, p2); b1v1 = p1; bi1 = pi; }
        else b2v1 = fminf(b2v1, p1);
    }

    if (tg == 0) {
        int rr = m * N_TOT + n_base + r0;
        g_idx[rr] = bi0; g_rowdist[rr] = b1v0;
        if (b2v0 - b1v0 <= MARGIN) {
            g_fbkey[rr] = ~0ull;
            int p = atomicAdd(&g_fbcnt[m], 1); g_fblist[m][p] = n_base + r0;
        }
        rr += 8;
        g_idx[rr] = bi1; g_rowdist[rr] = b1v1;
        if (b2v1 - b1v1 <= MARGIN) {
            g_fbkey[rr] = ~0ull;
            int p = atomicAdd(&g_fbcnt[m], 1); g_fblist[m][p] = n_base + r0 + 8;
        }
    }
}

// ---------------------------------------------------------------------------
// Exact fallback v3, chunk-parallel: block = (64-code chunk cx, row-tile ry, m).
// 16 KB code stage, persistent row loop, 64-code serial chain (half of v2).
// Reference-style quantized dist fl(fl(zn+en) - 2*dot), ascending-k strict <
// (lowest index), cross-block exact argmin via atomicMin on
// (dist_bits<<32 | idx): dist > 0 => float bits order-monotone; zn computed
// by an identical code path in every block => bit-identical keys.
// ---------------------------------------------------------------------------
__global__ __launch_bounds__(128)
void vq_fallback_kernel(const float* __restrict__ z, const float* __restrict__ cb)
{
    __shared__ float sc[64][64];
    __shared__ float sen[64];
    const int tid = threadIdx.x;
    const int cx = blockIdx.x;            // code chunk 0..15 (64 codes each)
    const int m  = blockIdx.z;
    const int cnt = g_fbcnt[m];
    if ((int)blockIdx.y * 128 >= cnt) return;

    // stage 64 codes (coalesced float4)
    const float4* src = reinterpret_cast<const float4*>(
        cb + ((size_t)m * NE + cx * 64) * E_DIM);
    for (int i = tid; i < 64 * 16; i += 128) {
        int code = i >> 4, q = i & 15;
        *reinterpret_cast<float4*>(&sc[code][q * 4]) = src[(size_t)code * 16 + q];
    }
    __syncthreads();
    if (tid < 64) {
        float s = 0.f;
        const float* cr = sc[tid];
        #pragma unroll
        for (int d = 0; d < 64; d++) s = __fmaf_rn(cr[d], cr[d], s);
        sen[tid] = s;
    }
    __syncthreads();

    for (int i = blockIdx.y * 128 + tid; i < cnt; i += 4 * 128) {
        int n = g_fblist[m][i];
        int r = m * N_TOT + n;
        int b = n >> 10, hw = n & 1023;
        const float* zp = z + (size_t)(b * C_TOT + m * E_DIM) * HW + hw;
        float zr[64];
        #pragma unroll
        for (int d = 0; d < 64; d++) zr[d] = zp[(size_t)d * HW];
        float zn = 0.f;
        #pragma unroll
        for (int d = 0; d < 64; d++) zn = __fmaf_rn(zr[d], zr[d], zn);

        float bv = 3.4e38f; int bc = 0;
        for (int c = 0; c < 64; c++) {               // ascending => lowest idx
            const float4* cr4 = reinterpret_cast<const float4*>(sc[c]);
            float d0 = 0.f, d1 = 0.f, d2 = 0.f, d3 = 0.f;
            #pragma unroll
            for (int q = 0; q < 16; q++) {
                float4 e = cr4[q];
                d0 = __fmaf_rn(zr[q * 4 + 0], e.x, d0);
                d1 = __fmaf_rn(zr[q * 4 + 1], e.y, d1);
                d2 = __fmaf_rn(zr[q * 4 + 2], e.z, d2);
                d3 = __fmaf_rn(zr[q * 4 + 3], e.w, d3);
            }
            float dot  = __fadd_rn(__fadd_rn(d0, d1), __fadd_rn(d2, d3));
            float dist = __fmaf_rn(-2.f, dot, __fadd_rn(zn, sen[c]));
            if (dist < bv) { bv = dist; bc = c; }
        }
        unsigned long long key =
            ((unsigned long long)__float_as_uint(bv) << 32)
            | (unsigned)(cx * 64 + bc);
        atomicMin(&g_fbkey[r], key);
    }
}

// ---------------------------------------------------------------------------
// Apply: decode winning keys into g_idx / g_rowdist (dist' convention).
// ---------------------------------------------------------------------------
__global__ __launch_bounds__(256)
void vq_apply_kernel(const float* __restrict__ z)
{
    const int m = blockIdx.y;
    const int cnt = g_fbcnt[m];
    for (int i = blockIdx.x * 256 + threadIdx.x; i < cnt; i += gridDim.x * 256) {
        int n = g_fblist[m][i];
        int r = m * N_TOT + n;
        unsigned long long key = g_fbkey[r];
        int   idx  = (int)(key & 0xFFFFFFFFull);
        float dist = __uint_as_float((unsigned)(key >> 32));
        int b = n >> 10, hw = n & 1023;
        const float* zp = z + (size_t)(b * C_TOT + m * E_DIM) * HW + hw;
        float zn = 0.f;
        #pragma unroll
        for (int d = 0; d < 64; d++) {
            float v = zp[(size_t)d * HW];
            zn = __fmaf_rn(v, v, zn);
        }
        g_idx[r] = idx;
        g_rowdist[r] = dist - zn;      // dist' convention
    }
}

// ---------------------------------------------------------------------------
// Scatter: gather chosen codes, straight-through rounding bit-exact
// (zq_st = fl(zf + fl(zq - zf))), scatter to NCHW, histogram,
// + deterministic per-tile sum of (z^2 + dist') for the loss.
// ---------------------------------------------------------------------------
#define ZS_STRIDE 68
__global__ __launch_bounds__(256)
void vq_scatter_kernel(const float* __restrict__ z, const float* __restrict__ cb,
                       float* __restrict__ out)
{
    __shared__ float cs[TM][ZS_STRIDE];
    __shared__ int   sidx[TM];
    __shared__ float red[256];
    const int tid = threadIdx.x;
    const int m = blockIdx.y, tile = blockIdx.x;
    const int n_base = tile * TM, b = n_base >> 10, hw0 = n_base & 1023;

    if (tid < TM) {
        int v = g_idx[m * N_TOT + n_base + tid];
        sidx[tid] = v;
        atomicAdd(&g_bins[v], 1);
    }
    __syncthreads();
    const float4* cb4 = reinterpret_cast<const float4*>(cb + (size_t)m * NE * E_DIM);
    for (int idx4 = tid; idx4 < TM * 16; idx4 += 256) {
        int r = idx4 >> 4, d4 = idx4 & 15;
        float4 v = cb4[sidx[r] * 16 + d4];
        *reinterpret_cast<float4*>(&cs[r][d4 * 4]) = v;
    }
    __syncthreads();
    const float* zsrc = z   + (size_t)(b * C_TOT + m * E_DIM) * HW + hw0;
    float*       dst  = out + (size_t)(b * C_TOT + m * E_DIM) * HW + hw0;
    float zs = 0.f;
    for (int idx = tid; idx < E_DIM * TM; idx += 256) {
        int d = idx >> 7, nl = idx & 127;
        size_t off = (size_t)d * HW + nl;
        float zv = zsrc[off];
        zs += zv * zv;
        float t  = __fsub_rn(cs[nl][d], zv);
        dst[off] = __fadd_rn(zv, t);
    }
    if (tid < TM) zs += g_rowdist[m * N_TOT + n_base + tid];   // fold dist'
    red[tid] = zs;
    __syncthreads();
    for (int s = 128; s >= 1; s >>= 1) {
        if (tid < s) red[tid] += red[tid + s];
        __syncthreads();
    }
    if (tid == 0) g_zpart[m * 128 + tile] = red[0];
}

// ---------------------------------------------------------------------------
// Final: loss = (sum of per-tile partials) * 1.25/(N*64) + dtype conversions.
// ---------------------------------------------------------------------------
__global__ __launch_bounds__(256)
void vq_final_kernel(float* __restrict__ out)
{
    if (blockIdx.x == 0) {
        __shared__ float part[256];
        int tid = threadIdx.x;
        float s = 0.f;
        #pragma unroll
        for (int q = 0; q < 4; q++) s += g_zpart[tid * 4 + q];
        part[tid] = s;
        __syncthreads();
        if (tid == 0) {
            float t = 0.f;
            for (int q = 0; q < 256; q++) t += part[q];
            out[OUT_LOSS] = t * (1.25f / (float)(N_TOT * E_DIM));
        }
    } else {
        int off = (blockIdx.x - 1) * 256 + threadIdx.x;
        if (off < M_SUB * N_TOT) {
            out[OUT_IDX + off] = (float)g_idx[off];
        } else {
            int bo = off - M_SUB * N_TOT;
            if (bo < NE) out[OUT_BIN + bo] = (float)g_bins[bo];
        }
    }
}

// ---------------------------------------------------------------------------
extern "C" void kernel_launch(void* const* d_in, const int* in_sizes, int n_in,
                              void* d_out, int out_size)
{
    const float* z  = (const float*)d_in[0];
    const float* cb = (const float*)d_in[1];
    float* out = (float*)d_out;

    cudaFuncSetAttribute(vq_tensor_kernel,
                         cudaFuncAttributeMaxDynamicSharedMemorySize, SMEM_BYTES);

    vq_init_kernel<<<5, 256>>>();
    vq_precompute_kernel<<<32, 256>>>(cb);

    dim3 gridT(N_TOT / TM, M_SUB);            // 128 x 8
    vq_tensor_kernel<<<gridT, 256, SMEM_BYTES>>>(z);

    dim3 gridF(16, 4, M_SUB);                 // 64-code chunk x row-tile x m
    vq_fallback_kernel<<<gridF, 128>>>(z, cb);

    dim3 gridA(4, M_SUB);
    vq_apply_kernel<<<gridA, 256>>>(z);

    dim3 gridS(N_TOT / TM, M_SUB);
    vq_scatter_kernel<<<gridS, 256>>>(z, cb, out);

    int conv_elems = M_SUB * N_TOT + NE;
    int gridC = 1 + (conv_elems + 255) / 256;
    vq_final_kernel<<<gridC, 256>>>(out);
}